// round 3
// baseline (speedup 1.0000x reference)
#include <cuda_runtime.h>
#include <cuda_bf16.h>
#include <cstdint>

// Problem constants
#define B_ 8
#define L_ 2048
#define DM_ 192
#define DI_ 384
#define N_ 16
#define R_ 12
#define M_ (B_ * L_)           // 16384 rows
#define NXZ_ (2 * DI_)          // 768
#define NC_ (R_ + 2 * N_)       // 44

// ---------------- scratch (static device allocations; no cudaMalloc) -------
__device__ float g_u[M_ * DI_];
__device__ float g_z[M_ * DI_];
__device__ float g_delta[M_ * DI_];
__device__ float g_Bs[M_ * N_];
__device__ float g_Cs[M_ * N_];
__device__ float g_y[M_ * DI_];
__device__ float g_yln[M_ * DI_];

// Packed f32x2 FMA (Blackwell FFMA2 — only reachable via PTX)
#define FMA_F32X2(d, a, b, c) \
    asm("fma.rn.f32x2 %0, %1, %2, %3;" : "=l"(d) : "l"(a), "l"(b), "l"(c))
#define UNPACK_F32X2M(lo, hi, v) \
    asm("mov.b64 {%0, %1}, %2;" : "=f"(lo), "=f"(hi) : "l"(v))

// ============================================================================
// Templated f32x2 GEMM:  Out[M, N] = act(A[M,K] @ W[N,K]^T)
//   BM x BN tile, BK=16, 256 threads, per-thread microtile 4m x 8n (4 f32x2).
//   A staged in smem duplicated ({a,a} pairs) -> both operands load as u64x2.
// ============================================================================
template<int BM, int BN, int KDIM, bool SILU, int LDO>
__global__ __launch_bounds__(256) void gemm_f32x2(
    const float* __restrict__ Amat, const float* __restrict__ Wmat,
    float* __restrict__ OutU, float* __restrict__ OutZ)
{
    __shared__ float As2[16][2 * BM + 4];   // duplicated pairs, +4 pad
    __shared__ float Ws[16][BN + 4];        // +4 pad

    const int tid = threadIdx.x;
    const int bm = blockIdx.x * BM;
    const int bn = blockIdx.y * BN;

    constexpr int TXN = BN / 8;             // threads in n dir
    const int tx = tid % TXN;
    const int ty = tid / TXN;
    const int m0 = ty * 4;
    const int n0 = tx * 8;

    unsigned long long acc[4][4];
#pragma unroll
    for (int i = 0; i < 4; i++)
#pragma unroll
        for (int j = 0; j < 4; j++) acc[i][j] = 0ull;

    for (int k0 = 0; k0 < KDIM; k0 += 16) {
        // stage A (duplicated) : BM rows x 16 k
#pragma unroll
        for (int it = 0; it < (BM * 4) / 256; ++it) {
            const int idx = tid + it * 256;
            const int row = idx >> 2;
            const int c4 = (idx & 3) * 4;
            float4 v = *(const float4*)&Amat[(size_t)(bm + row) * KDIM + k0 + c4];
            As2[c4 + 0][2 * row] = v.x; As2[c4 + 0][2 * row + 1] = v.x;
            As2[c4 + 1][2 * row] = v.y; As2[c4 + 1][2 * row + 1] = v.y;
            As2[c4 + 2][2 * row] = v.z; As2[c4 + 2][2 * row + 1] = v.z;
            As2[c4 + 3][2 * row] = v.w; As2[c4 + 3][2 * row + 1] = v.w;
        }
        // stage W : BN rows x 16 k
#pragma unroll
        for (int it = 0; it < (BN * 4) / 256; ++it) {
            const int idx = tid + it * 256;
            const int row = idx >> 2;
            const int c4 = (idx & 3) * 4;
            float4 v = *(const float4*)&Wmat[(size_t)(bn + row) * KDIM + k0 + c4];
            Ws[c4 + 0][row] = v.x;
            Ws[c4 + 1][row] = v.y;
            Ws[c4 + 2][row] = v.z;
            Ws[c4 + 3][row] = v.w;
        }
        __syncthreads();

#pragma unroll
        for (int kk = 0; kk < 16; ++kk) {
            const ulonglong2 a01 = *(const ulonglong2*)&As2[kk][2 * m0];
            const ulonglong2 a23 = *(const ulonglong2*)&As2[kk][2 * m0 + 4];
            const ulonglong2 w01 = *(const ulonglong2*)&Ws[kk][n0];
            const ulonglong2 w23 = *(const ulonglong2*)&Ws[kk][n0 + 4];
            const unsigned long long aa[4] = {a01.x, a01.y, a23.x, a23.y};
            const unsigned long long ww[4] = {w01.x, w01.y, w23.x, w23.y};
#pragma unroll
            for (int i = 0; i < 4; i++)
#pragma unroll
                for (int j = 0; j < 4; j++)
                    FMA_F32X2(acc[i][j], aa[i], ww[j], acc[i][j]);
        }
        __syncthreads();
    }

    // epilogue
#pragma unroll
    for (int i = 0; i < 4; i++) {
        float o[8];
#pragma unroll
        for (int j = 0; j < 4; j++)
            UNPACK_F32X2M(o[2 * j], o[2 * j + 1], acc[i][j]);
        if (SILU) {
#pragma unroll
            for (int e = 0; e < 8; e++)
                o[e] = o[e] / (1.f + __expf(-o[e]));
        }
        const int m = bm + m0 + i;
        float4 v0 = make_float4(o[0], o[1], o[2], o[3]);
        float4 v1 = make_float4(o[4], o[5], o[6], o[7]);
        if (!SILU || bn < DI_) {
            const int col = SILU ? (bn + n0) : (bn + n0);
            *(float4*)&OutU[(size_t)m * LDO + col] = v0;
            *(float4*)&OutU[(size_t)m * LDO + col + 4] = v1;
        } else {
            const int col = bn + n0 - DI_;
            *(float4*)&OutZ[(size_t)m * LDO + col] = v0;
            *(float4*)&OutZ[(size_t)m * LDO + col + 4] = v1;
        }
    }
}

// ============================================================================
// K2: warp-per-column projection. Coalesced XPW reads, shfl reduction.
// ============================================================================
#define K2_ROWS 16

__device__ __forceinline__ float softplusf(float x) {
    return (x > 20.f) ? x : log1pf(__expf(x));
}

__global__ __launch_bounds__(256) void k2_proj(
    const float* __restrict__ U, const float* __restrict__ XPW,
    const float* __restrict__ DTW, const float* __restrict__ DTB,
    float* __restrict__ Delta, float* __restrict__ Bs, float* __restrict__ Cs)
{
    __shared__ float su[K2_ROWS][DI_];
    __shared__ float sdbl[K2_ROWS][NC_];
    __shared__ float sdtw[DI_ * R_];
    __shared__ float sdtb[DI_];

    const int tid = threadIdx.x;
    const int row0 = blockIdx.x * K2_ROWS;
    const int warp = tid >> 5, lane = tid & 31;

    for (int i = tid; i < K2_ROWS * DI_; i += 256) {
        int r = i / DI_, k = i % DI_;
        su[r][k] = U[(size_t)(row0 + r) * DI_ + k];
    }
    for (int i = tid; i < DI_ * R_; i += 256) sdtw[i] = DTW[i];
    for (int i = tid; i < DI_; i += 256) sdtb[i] = DTB[i];
    __syncthreads();

    for (int c = warp; c < NC_; c += 8) {
        const float* wr = XPW + (size_t)c * DI_;
        float acc[K2_ROWS];
#pragma unroll
        for (int r = 0; r < K2_ROWS; r++) acc[r] = 0.f;
#pragma unroll
        for (int i = 0; i < DI_ / 32; i++) {
            const int k = i * 32 + lane;
            const float w = wr[k];
#pragma unroll
            for (int r = 0; r < K2_ROWS; r++)
                acc[r] = fmaf(su[r][k], w, acc[r]);
        }
#pragma unroll
        for (int r = 0; r < K2_ROWS; r++) {
            float v = acc[r];
#pragma unroll
            for (int o = 16; o; o >>= 1) v += __shfl_xor_sync(0xffffffffu, v, o);
            if (lane == 0) sdbl[r][c] = v;
        }
    }
    __syncthreads();

    for (int o = tid; o < K2_ROWS * 2 * N_; o += 256) {
        int r = o / (2 * N_), c = o % (2 * N_);
        float v = sdbl[r][R_ + c];
        if (c < N_) Bs[(size_t)(row0 + r) * N_ + c] = v;
        else        Cs[(size_t)(row0 + r) * N_ + (c - N_)] = v;
    }

    for (int o = tid; o < K2_ROWS * DI_; o += 256) {
        int r = o / DI_, d = o % DI_;
        float acc = sdtb[d];
        const float* wd = &sdtw[d * R_];
#pragma unroll
        for (int j = 0; j < R_; j++) acc = fmaf(sdbl[r][j], wd[j], acc);
        Delta[(size_t)(row0 + r) * DI_ + d] = softplusf(acc);
    }
}

// ============================================================================
// K3: selective scan. 16 lanes per (b,d) group over n.
// ============================================================================
__global__ __launch_bounds__(256) void k3_scan(
    const float* __restrict__ Delta, const float* __restrict__ U,
    const float* __restrict__ Bsg, const float* __restrict__ Csg,
    const float* __restrict__ A_logs, const float* __restrict__ Ds,
    float* __restrict__ Y)
{
    const int tid = threadIdx.x;
    const int grp = (blockIdx.x * blockDim.x + tid) >> 4;
    const int n = tid & 15;
    const int b = grp / DI_;
    const int d = grp - b * DI_;

    const float A = -__expf(A_logs[d * N_ + n]);
    const float Dd = Ds[d];

    const float* dptr = Delta + (size_t)b * L_ * DI_ + d;
    const float* uptr = U     + (size_t)b * L_ * DI_ + d;
    const float* bptr = Bsg   + (size_t)b * L_ * N_ + n;
    const float* cptr = Csg   + (size_t)b * L_ * N_ + n;
    float* yptr       = Y     + (size_t)b * L_ * DI_ + d;

    float h = 0.f;
#pragma unroll 4
    for (int t = 0; t < L_; t++) {
        const float delta = dptr[(size_t)t * DI_];
        const float u     = uptr[(size_t)t * DI_];
        const float Bv    = bptr[(size_t)t * N_];
        const float Cv    = cptr[(size_t)t * N_];
        const float dA = __expf(delta * A);
        h = fmaf(dA, h, delta * u * Bv);
        float y = h * Cv;
        y += __shfl_xor_sync(0xffffffffu, y, 8, 16);
        y += __shfl_xor_sync(0xffffffffu, y, 4, 16);
        y += __shfl_xor_sync(0xffffffffu, y, 2, 16);
        y += __shfl_xor_sync(0xffffffffu, y, 1, 16);
        if (n == 0) yptr[(size_t)t * DI_] = fmaf(Dd, u, y);
    }
}

// ============================================================================
// K4a: yln = (LayerNorm(y) * gamma + beta) * z
// ============================================================================
__global__ __launch_bounds__(256) void k4a_ln(
    const float* __restrict__ Y, const float* __restrict__ Zg,
    const float* __restrict__ gamma, const float* __restrict__ beta,
    float* __restrict__ Yln)
{
    const int tid = threadIdx.x;
    const int warp = tid >> 5, lane = tid & 31;
    const int row = blockIdx.x * 8 + warp;

    const float* yr = Y   + (size_t)row * DI_;
    const float* zr = Zg  + (size_t)row * DI_;
    float* outr     = Yln + (size_t)row * DI_;

    float v[12];
    float sum = 0.f, sq = 0.f;
#pragma unroll
    for (int i = 0; i < 12; i++) {
        float t = yr[lane + i * 32];
        v[i] = t; sum += t; sq = fmaf(t, t, sq);
    }
#pragma unroll
    for (int o = 16; o; o >>= 1) {
        sum += __shfl_xor_sync(0xffffffffu, sum, o);
        sq  += __shfl_xor_sync(0xffffffffu, sq, o);
    }
    const float mu = sum * (1.f / DI_);
    const float var = sq * (1.f / DI_) - mu * mu;
    const float rs = rsqrtf(var + 1e-5f);
#pragma unroll
    for (int i = 0; i < 12; i++) {
        int k = lane + i * 32;
        outr[k] = fmaf((v[i] - mu) * rs, gamma[k], beta[k]) * zr[k];
    }
}

// ============================================================================
extern "C" void kernel_launch(void* const* d_in, const int* in_sizes, int n_in,
                              void* d_out, int out_size)
{
    const float* x         = (const float*)d_in[0];
    const float* W_in      = (const float*)d_in[1];
    const float* x_proj_w  = (const float*)d_in[2];
    const float* dt_proj_w = (const float*)d_in[3];
    const float* dt_proj_b = (const float*)d_in[4];
    const float* A_logs    = (const float*)d_in[5];
    const float* Ds        = (const float*)d_in[6];
    const float* ln_gamma  = (const float*)d_in[7];
    const float* ln_beta   = (const float*)d_in[8];
    const float* W_out     = (const float*)d_in[9];
    float* out = (float*)d_out;

    float *u, *z, *delta, *bs, *cs, *y, *yln;
    cudaGetSymbolAddress((void**)&u, g_u);
    cudaGetSymbolAddress((void**)&z, g_z);
    cudaGetSymbolAddress((void**)&delta, g_delta);
    cudaGetSymbolAddress((void**)&bs, g_Bs);
    cudaGetSymbolAddress((void**)&cs, g_Cs);
    cudaGetSymbolAddress((void**)&y, g_y);
    cudaGetSymbolAddress((void**)&yln, g_yln);

    // K1: silu(x @ W_in^T) -> u | z.  64x128 tiles.
    dim3 g1(M_ / 64, NXZ_ / 128);
    gemm_f32x2<64, 128, DM_, true, DI_><<<g1, 256>>>(x, W_in, u, z);

    k2_proj<<<M_ / K2_ROWS, 256>>>(u, x_proj_w, dt_proj_w, dt_proj_b,
                                   delta, bs, cs);

    k3_scan<<<(B_ * DI_ * 16) / 256, 256>>>(delta, u, bs, cs, A_logs, Ds, y);

    k4a_ln<<<M_ / 8, 256>>>(y, z, ln_gamma, ln_beta, yln);

    // K4b: yln @ W_out^T.  128x64 tiles.
    dim3 g4(M_ / 128, DM_ / 64);
    gemm_f32x2<128, 64, DI_, false, DM_><<<g4, 256>>>(yln, W_out, out, nullptr);
}

// round 5
// speedup vs baseline: 1.3066x; 1.3066x over previous
#include <cuda_runtime.h>
#include <cuda_bf16.h>
#include <cstdint>

// Problem constants
#define B_ 8
#define L_ 2048
#define DM_ 192
#define DI_ 384
#define N_ 16
#define R_ 12
#define M_ (B_ * L_)           // 16384 rows
#define NXZ_ (2 * DI_)          // 768
#define NC_ (R_ + 2 * N_)       // 44

// ---------------- scratch (static device allocations; no cudaMalloc) -------
__device__ float g_u[M_ * DI_];
__device__ float g_z[M_ * DI_];
__device__ float g_delta[M_ * DI_];
__device__ float g_Bs[M_ * N_];
__device__ float g_Cs[M_ * N_];
__device__ float g_y[M_ * DI_];
__device__ __nv_bfloat16 g_xhi[M_ * DM_];
__device__ __nv_bfloat16 g_xlo[M_ * DM_];
__device__ __nv_bfloat16 g_whi[NXZ_ * DM_];
__device__ __nv_bfloat16 g_wlo[NXZ_ * DM_];
__device__ __nv_bfloat16 g_yhi[M_ * DI_];
__device__ __nv_bfloat16 g_ylo[M_ * DI_];
__device__ __nv_bfloat16 g_wohi[DM_ * DI_];
__device__ __nv_bfloat16 g_wolo[DM_ * DI_];

// ============================================================================
// helpers
// ============================================================================
__device__ __forceinline__ uint32_t smem_u32(const void* p) {
    uint32_t a;
    asm("{ .reg .u64 t; cvta.to.shared.u64 t, %1; cvt.u32.u64 %0, t; }"
        : "=r"(a) : "l"(p));
    return a;
}

__device__ __forceinline__ void ldm_x4(uint32_t* r, uint32_t addr) {
    asm volatile("ldmatrix.sync.aligned.m8n8.x4.shared.b16 {%0,%1,%2,%3}, [%4];"
        : "=r"(r[0]), "=r"(r[1]), "=r"(r[2]), "=r"(r[3]) : "r"(addr));
}
__device__ __forceinline__ void ldm_x2(uint32_t* r, uint32_t addr) {
    asm volatile("ldmatrix.sync.aligned.m8n8.x2.shared.b16 {%0,%1}, [%2];"
        : "=r"(r[0]), "=r"(r[1]) : "r"(addr));
}
__device__ __forceinline__ void mma16816(float* c, const uint32_t* a, const uint32_t* b) {
    asm volatile(
        "mma.sync.aligned.m16n8k16.row.col.f32.bf16.bf16.f32 "
        "{%0,%1,%2,%3}, {%4,%5,%6,%7}, {%8,%9}, {%0,%1,%2,%3};"
        : "+f"(c[0]), "+f"(c[1]), "+f"(c[2]), "+f"(c[3])
        : "r"(a[0]), "r"(a[1]), "r"(a[2]), "r"(a[3]), "r"(b[0]), "r"(b[1]));
}

// ============================================================================
// K0: fp32 -> bf16 hi + residual lo
// ============================================================================
__global__ __launch_bounds__(256) void conv_split(
    const float* __restrict__ src, __nv_bfloat16* __restrict__ hi,
    __nv_bfloat16* __restrict__ lo, int n4)
{
    int i = blockIdx.x * blockDim.x + threadIdx.x;
    if (i >= n4) return;
    float4 v = ((const float4*)src)[i];
    __nv_bfloat162 h0, h1, l0, l1;
    h0.x = __float2bfloat16_rn(v.x); h0.y = __float2bfloat16_rn(v.y);
    h1.x = __float2bfloat16_rn(v.z); h1.y = __float2bfloat16_rn(v.w);
    l0.x = __float2bfloat16_rn(v.x - __bfloat162float(h0.x));
    l0.y = __float2bfloat16_rn(v.y - __bfloat162float(h0.y));
    l1.x = __float2bfloat16_rn(v.z - __bfloat162float(h1.x));
    l1.y = __float2bfloat16_rn(v.w - __bfloat162float(h1.y));
    ((__nv_bfloat162*)hi)[2 * i] = h0; ((__nv_bfloat162*)hi)[2 * i + 1] = h1;
    ((__nv_bfloat162*)lo)[2 * i] = l0; ((__nv_bfloat162*)lo)[2 * i + 1] = l1;
}

// ============================================================================
// Tensor-core GEMM via mma.sync (bf16 split, fp32 accum):
//   Out[M,N] = act( A[M,K] @ W[N,K]^T ),  A = Ahi+Alo, W = Whi+Wlo
//   acc = Ahi*Whi + Ahi*Wlo + Alo*Whi
//   256 threads = 8 warps (4 x 2), warp tile (BM/4) x (BN/2), BK=32.
// ============================================================================
#define LDSB 40   // padded smem row length in bf16 (80 B: conflict-free ldmatrix)

template<int BM, int BN, int KDIM, bool SILU, int LDO>
__global__ __launch_bounds__(256) void gemm_mma(
    const __nv_bfloat16* __restrict__ Ahi, const __nv_bfloat16* __restrict__ Alo,
    const __nv_bfloat16* __restrict__ Whi, const __nv_bfloat16* __restrict__ Wlo,
    float* __restrict__ OutU, float* __restrict__ OutZ)
{
    constexpr int WM = BM / 4;
    constexpr int WN = BN / 2;
    constexpr int MI = WM / 16;
    constexpr int NI = WN / 8;

    __shared__ __align__(16) __nv_bfloat16 sAh[BM * LDSB];
    __shared__ __align__(16) __nv_bfloat16 sAl[BM * LDSB];
    __shared__ __align__(16) __nv_bfloat16 sWh[BN * LDSB];
    __shared__ __align__(16) __nv_bfloat16 sWl[BN * LDSB];

    const int tid = threadIdx.x;
    const int wid = tid >> 5, lane = tid & 31;
    const int wr = wid >> 1, wc = wid & 1;
    const int bm = blockIdx.x * BM;
    const int bn = blockIdx.y * BN;

    const uint32_t sAh32 = smem_u32(sAh), sAl32 = smem_u32(sAl);
    const uint32_t sWh32 = smem_u32(sWh), sWl32 = smem_u32(sWl);

    float acc[MI][NI][4];
#pragma unroll
    for (int i = 0; i < MI; i++)
#pragma unroll
        for (int j = 0; j < NI; j++)
#pragma unroll
            for (int e = 0; e < 4; e++) acc[i][j][e] = 0.f;

    for (int k0 = 0; k0 < KDIM; k0 += 32) {
        // ---- stage A (BM x 32) and W (BN x 32), 16B chunks ----
#pragma unroll
        for (int idx = tid; idx < BM * 4; idx += 256) {
            const int row = idx >> 2, c = idx & 3;
            const size_t go = (size_t)(bm + row) * KDIM + k0 + c * 8;
            const int so = row * LDSB + c * 8;
            *(float4*)&sAh[so] = *(const float4*)&Ahi[go];
            *(float4*)&sAl[so] = *(const float4*)&Alo[go];
        }
#pragma unroll
        for (int idx = tid; idx < BN * 4; idx += 256) {
            const int row = idx >> 2, c = idx & 3;
            const size_t go = (size_t)(bn + row) * KDIM + k0 + c * 8;
            const int so = row * LDSB + c * 8;
            *(float4*)&sWh[so] = *(const float4*)&Whi[go];
            *(float4*)&sWl[so] = *(const float4*)&Wlo[go];
        }
        __syncthreads();

#pragma unroll
        for (int ks = 0; ks < 32; ks += 16) {
            uint32_t ah[MI][4], al[MI][4];
#pragma unroll
            for (int mi = 0; mi < MI; mi++) {
                const int row = wr * WM + mi * 16 + (lane & 15);
                const int col = ks + ((lane >> 4) << 3);
                const uint32_t off = (uint32_t)(row * LDSB + col) * 2;
                ldm_x4(ah[mi], sAh32 + off);
                ldm_x4(al[mi], sAl32 + off);
            }
            uint32_t bh[NI][2], bl[NI][2];
#pragma unroll
            for (int ni = 0; ni < NI; ni++) {
                const int row = wc * WN + ni * 8 + (lane & 7);
                const int col = ks + ((lane >> 3) & 1) * 8;
                const uint32_t off = (uint32_t)(row * LDSB + col) * 2;
                ldm_x2(bh[ni], sWh32 + off);
                ldm_x2(bl[ni], sWl32 + off);
            }
#pragma unroll
            for (int mi = 0; mi < MI; mi++)
#pragma unroll
                for (int ni = 0; ni < NI; ni++) {
                    mma16816(acc[mi][ni], ah[mi], bh[ni]);
                    mma16816(acc[mi][ni], ah[mi], bl[ni]);
                    mma16816(acc[mi][ni], al[mi], bh[ni]);
                }
        }
        __syncthreads();
    }

    // ---- epilogue ----
    const int g = lane >> 2, tig = lane & 3;
#pragma unroll
    for (int mi = 0; mi < MI; mi++) {
#pragma unroll
        for (int ni = 0; ni < NI; ni++) {
            const int row = bm + wr * WM + mi * 16 + g;
            const int colg = bn + wc * WN + ni * 8 + tig * 2;
            float o0 = acc[mi][ni][0], o1 = acc[mi][ni][1];
            float o2 = acc[mi][ni][2], o3 = acc[mi][ni][3];
            if (SILU) {
                o0 = o0 / (1.f + __expf(-o0));
                o1 = o1 / (1.f + __expf(-o1));
                o2 = o2 / (1.f + __expf(-o2));
                o3 = o3 / (1.f + __expf(-o3));
            }
            float* dst;
            int col;
            if (SILU && colg >= DI_) { dst = OutZ; col = colg - DI_; }
            else                     { dst = OutU; col = colg; }
            *(float2*)&dst[(size_t)row * LDO + col] = make_float2(o0, o1);
            *(float2*)&dst[(size_t)(row + 8) * LDO + col] = make_float2(o2, o3);
        }
    }
}

// ============================================================================
// K2: warp-per-column projection (known-good)
// ============================================================================
#define K2_ROWS 16

__device__ __forceinline__ float softplusf(float x) {
    return (x > 20.f) ? x : log1pf(__expf(x));
}

__global__ __launch_bounds__(256) void k2_proj(
    const float* __restrict__ U, const float* __restrict__ XPW,
    const float* __restrict__ DTW, const float* __restrict__ DTB,
    float* __restrict__ Delta, float* __restrict__ Bs, float* __restrict__ Cs)
{
    __shared__ float su[K2_ROWS][DI_];
    __shared__ float sdbl[K2_ROWS][NC_];
    __shared__ float sdtw[DI_ * R_];
    __shared__ float sdtb[DI_];

    const int tid = threadIdx.x;
    const int row0 = blockIdx.x * K2_ROWS;
    const int warp = tid >> 5, lane = tid & 31;

    for (int i = tid; i < K2_ROWS * DI_; i += 256) {
        int r = i / DI_, k = i % DI_;
        su[r][k] = U[(size_t)(row0 + r) * DI_ + k];
    }
    for (int i = tid; i < DI_ * R_; i += 256) sdtw[i] = DTW[i];
    for (int i = tid; i < DI_; i += 256) sdtb[i] = DTB[i];
    __syncthreads();

    for (int c = warp; c < NC_; c += 8) {
        const float* wr = XPW + (size_t)c * DI_;
        float acc[K2_ROWS];
#pragma unroll
        for (int r = 0; r < K2_ROWS; r++) acc[r] = 0.f;
#pragma unroll
        for (int i = 0; i < DI_ / 32; i++) {
            const int k = i * 32 + lane;
            const float w = wr[k];
#pragma unroll
            for (int r = 0; r < K2_ROWS; r++)
                acc[r] = fmaf(su[r][k], w, acc[r]);
        }
#pragma unroll
        for (int r = 0; r < K2_ROWS; r++) {
            float v = acc[r];
#pragma unroll
            for (int o = 16; o; o >>= 1) v += __shfl_xor_sync(0xffffffffu, v, o);
            if (lane == 0) sdbl[r][c] = v;
        }
    }
    __syncthreads();

    for (int o = tid; o < K2_ROWS * 2 * N_; o += 256) {
        int r = o / (2 * N_), c = o % (2 * N_);
        float v = sdbl[r][R_ + c];
        if (c < N_) Bs[(size_t)(row0 + r) * N_ + c] = v;
        else        Cs[(size_t)(row0 + r) * N_ + (c - N_)] = v;
    }

    for (int o = tid; o < K2_ROWS * DI_; o += 256) {
        int r = o / DI_, d = o % DI_;
        float acc = sdtb[d];
        const float* wd = &sdtw[d * R_];
#pragma unroll
        for (int j = 0; j < R_; j++) acc = fmaf(sdbl[r][j], wd[j], acc);
        Delta[(size_t)(row0 + r) * DI_ + d] = softplusf(acc);
    }
}

// ============================================================================
// K3: selective scan (known-good)
// ============================================================================
__global__ __launch_bounds__(256) void k3_scan(
    const float* __restrict__ Delta, const float* __restrict__ U,
    const float* __restrict__ Bsg, const float* __restrict__ Csg,
    const float* __restrict__ A_logs, const float* __restrict__ Ds,
    float* __restrict__ Y)
{
    const int tid = threadIdx.x;
    const int grp = (blockIdx.x * blockDim.x + tid) >> 4;
    const int n = tid & 15;
    const int b = grp / DI_;
    const int d = grp - b * DI_;

    const float A = -__expf(A_logs[d * N_ + n]);
    const float Dd = Ds[d];

    const float* dptr = Delta + (size_t)b * L_ * DI_ + d;
    const float* uptr = U     + (size_t)b * L_ * DI_ + d;
    const float* bptr = Bsg   + (size_t)b * L_ * N_ + n;
    const float* cptr = Csg   + (size_t)b * L_ * N_ + n;
    float* yptr       = Y     + (size_t)b * L_ * DI_ + d;

    float h = 0.f;
#pragma unroll 4
    for (int t = 0; t < L_; t++) {
        const float delta = dptr[(size_t)t * DI_];
        const float u     = uptr[(size_t)t * DI_];
        const float Bv    = bptr[(size_t)t * N_];
        const float Cv    = cptr[(size_t)t * N_];
        const float dA = __expf(delta * A);
        h = fmaf(dA, h, delta * u * Bv);
        float y = h * Cv;
        y += __shfl_xor_sync(0xffffffffu, y, 8, 16);
        y += __shfl_xor_sync(0xffffffffu, y, 4, 16);
        y += __shfl_xor_sync(0xffffffffu, y, 2, 16);
        y += __shfl_xor_sync(0xffffffffu, y, 1, 16);
        if (n == 0) yptr[(size_t)t * DI_] = fmaf(Dd, u, y);
    }
}

// ============================================================================
// K4a: yln = (LayerNorm(y)*gamma+beta)*z, emitted as bf16 hi/lo split
// ============================================================================
__global__ __launch_bounds__(256) void k4a_ln(
    const float* __restrict__ Y, const float* __restrict__ Zg,
    const float* __restrict__ gamma, const float* __restrict__ beta,
    __nv_bfloat16* __restrict__ Yhi, __nv_bfloat16* __restrict__ Ylo)
{
    const int tid = threadIdx.x;
    const int warp = tid >> 5, lane = tid & 31;
    const int row = blockIdx.x * 8 + warp;

    const float* yr = Y  + (size_t)row * DI_;
    const float* zr = Zg + (size_t)row * DI_;
    __nv_bfloat16* hr = Yhi + (size_t)row * DI_;
    __nv_bfloat16* lr = Ylo + (size_t)row * DI_;

    float v[12];
    float sum = 0.f, sq = 0.f;
#pragma unroll
    for (int i = 0; i < 12; i++) {
        float t = yr[lane + i * 32];
        v[i] = t; sum += t; sq = fmaf(t, t, sq);
    }
#pragma unroll
    for (int o = 16; o; o >>= 1) {
        sum += __shfl_xor_sync(0xffffffffu, sum, o);
        sq  += __shfl_xor_sync(0xffffffffu, sq, o);
    }
    const float mu = sum * (1.f / DI_);
    const float var = sq * (1.f / DI_) - mu * mu;
    const float rs = rsqrtf(var + 1e-5f);
#pragma unroll
    for (int i = 0; i < 12; i++) {
        int k = lane + i * 32;
        float r = fmaf((v[i] - mu) * rs, gamma[k], beta[k]) * zr[k];
        __nv_bfloat16 h = __float2bfloat16_rn(r);
        hr[k] = h;
        lr[k] = __float2bfloat16_rn(r - __bfloat162float(h));
    }
}

// ============================================================================
extern "C" void kernel_launch(void* const* d_in, const int* in_sizes, int n_in,
                              void* d_out, int out_size)
{
    const float* x         = (const float*)d_in[0];
    const float* W_in      = (const float*)d_in[1];
    const float* x_proj_w  = (const float*)d_in[2];
    const float* dt_proj_w = (const float*)d_in[3];
    const float* dt_proj_b = (const float*)d_in[4];
    const float* A_logs    = (const float*)d_in[5];
    const float* Ds        = (const float*)d_in[6];
    const float* ln_gamma  = (const float*)d_in[7];
    const float* ln_beta   = (const float*)d_in[8];
    const float* W_out     = (const float*)d_in[9];
    float* out = (float*)d_out;

    float *u, *z, *delta, *bs, *cs, *y;
    __nv_bfloat16 *xhi, *xlo, *whi, *wlo, *yhi, *ylo, *wohi, *wolo;
    cudaGetSymbolAddress((void**)&u, g_u);
    cudaGetSymbolAddress((void**)&z, g_z);
    cudaGetSymbolAddress((void**)&delta, g_delta);
    cudaGetSymbolAddress((void**)&bs, g_Bs);
    cudaGetSymbolAddress((void**)&cs, g_Cs);
    cudaGetSymbolAddress((void**)&y, g_y);
    cudaGetSymbolAddress((void**)&xhi, g_xhi);
    cudaGetSymbolAddress((void**)&xlo, g_xlo);
    cudaGetSymbolAddress((void**)&whi, g_whi);
    cudaGetSymbolAddress((void**)&wlo, g_wlo);
    cudaGetSymbolAddress((void**)&yhi, g_yhi);
    cudaGetSymbolAddress((void**)&ylo, g_ylo);
    cudaGetSymbolAddress((void**)&wohi, g_wohi);
    cudaGetSymbolAddress((void**)&wolo, g_wolo);

    // splits for K1
    conv_split<<<(M_ * DM_ / 4 + 255) / 256, 256>>>(x, xhi, xlo, M_ * DM_ / 4);
    conv_split<<<(NXZ_ * DM_ / 4 + 255) / 256, 256>>>(W_in, whi, wlo, NXZ_ * DM_ / 4);

    // K1: u|z = silu(x @ W_in^T)   [tensor core]
    dim3 g1(M_ / 128, NXZ_ / 128);
    gemm_mma<128, 128, DM_, true, DI_><<<g1, 256>>>(xhi, xlo, whi, wlo, u, z);

    k2_proj<<<M_ / K2_ROWS, 256>>>(u, x_proj_w, dt_proj_w, dt_proj_b,
                                   delta, bs, cs);

    k3_scan<<<(B_ * DI_ * 16) / 256, 256>>>(delta, u, bs, cs, A_logs, Ds, y);

    // split for K4b weights (can run anytime before k4b)
    conv_split<<<(DM_ * DI_ / 4 + 255) / 256, 256>>>(W_out, wohi, wolo, DM_ * DI_ / 4);

    k4a_ln<<<M_ / 8, 256>>>(y, z, ln_gamma, ln_beta, yhi, ylo);

    // K4b: out = yln @ W_out^T   [tensor core]
    dim3 g4(M_ / 128, DM_ / 64);
    gemm_mma<128, 64, DI_, false, DM_><<<g4, 256>>>(yhi, ylo, wohi, wolo, out, nullptr);
}